// round 13
// baseline (speedup 1.0000x reference)
#include <cuda_runtime.h>
#include <cuda_bf16.h>
#include <cstdint>

#define NTOK   65536
#define NSLOT  4096
#define DDIM   768
#define LN_EPS 1e-5f

// GEMM tiling: cta_group::2 clusters. Cluster tile = M 256 x N 256; per CTA M/N half = 128.
#define KCH     32
#define NCHUNK  (DDIM / KCH)           // 24
#define NBUF    4
#define LEAD    3
#define SZ_T    (128 * 64)             // 8192 B: one 128-row x 32-col bf16 SW64 tile
#define SZ_BUF  (4 * SZ_T)             // 32768: AH, AL, BH, BL per chunk per CTA

// ---- tcgen05 capability gate (per device-compile pass) ----
#if (defined(__CUDA_ARCH_SPECIFIC__) && (__CUDA_ARCH_SPECIFIC__ >= 1000)) || \
    (defined(__CUDA_ARCH_FAMILY_SPECIFIC__) && (__CUDA_ARCH_FAMILY_SPECIFIC__ >= 1000)) || \
    defined(__CUDA_ARCH_FEAT_SM100_ALL) || defined(__CUDA_ARCH_FEAT_SM101_ALL) || \
    defined(__CUDA_ARCH_FEAT_SM103_ALL)
#define HAS_TCGEN05 1
#else
#define HAS_TCGEN05 0
#endif

// ---------------- device scratch (128-row tiles, SW64 pre-swizzled) ----------------
// tile t (128 rows), chunk c: byte offset (t*NCHUNK + c)*SZ_T
__device__ __align__(1024) __nv_bfloat16 g_ahi[(size_t)NSLOT * DDIM];
__device__ __align__(1024) __nv_bfloat16 g_alo[(size_t)NSLOT * DDIM];
__device__ __align__(1024) __nv_bfloat16 g_whi[(size_t)DDIM * DDIM];
__device__ __align__(1024) __nv_bfloat16 g_wlo[(size_t)DDIM * DDIM];
__device__ int g_segstart[NSLOT + 1];

// ---------------- PTX helpers ----------------
__device__ __forceinline__ uint32_t smem_u32(const void* p) {
    uint32_t a;
    asm("{ .reg .u64 t; cvta.to.shared.u64 t, %1; cvt.u32.u64 %0, t; }" : "=r"(a) : "l"(p));
    return a;
}

__device__ __forceinline__ uint32_t sw64(uint32_t off) {
    return off ^ ((off >> 3) & 0x30);
}

#if HAS_TCGEN05

__device__ __forceinline__ uint32_t cluster_rank() {
    uint32_t r;
    asm("mov.u32 %0, %%cluster_ctarank;" : "=r"(r));
    return r;
}

#define MBARRIER_INIT(addr, cnt) \
    asm volatile("mbarrier.init.shared.b64 [%0], %1;" :: "r"(addr), "r"(cnt) : "memory")

#define MBARRIER_EXPECT_TX(addr, bytes) \
    asm volatile("mbarrier.arrive.expect_tx.shared.b64 _, [%0], %1;" \
                 :: "r"(addr), "r"(bytes) : "memory")

// Arrive on the same-offset mbarrier in cluster CTA rank 0.
#define MBARRIER_ARRIVE_RANK0(local_addr) \
    asm volatile("{\n .reg .b32 ra;\n mapa.shared::cluster.u32 ra, %0, 0;\n" \
        " mbarrier.arrive.shared::cluster.b64 _, [ra];\n}" \
        :: "r"(local_addr) : "memory")

#define MBARRIER_WAIT_PARITY(mbar, parity) do {                                   \
    uint32_t _m = (mbar); uint32_t _p = (parity); uint32_t _done;                 \
    asm volatile("{\n .reg .pred p;\n"                                            \
        " mbarrier.try_wait.parity.acquire.cta.shared::cta.b64 p, [%1], %2;\n"    \
        " selp.b32 %0, 1, 0, p;\n}"                                               \
        : "=r"(_done) : "r"(_m), "r"(_p) : "memory");                             \
    if (!_done) {                                                                 \
        asm volatile("{\n .reg .pred P1;\n"                                       \
            "WL_%=:\n"                                                            \
            " mbarrier.try_wait.parity.acquire.cta.shared::cta.b64 P1, [%0], %1, 0x989680;\n" \
            " @P1 bra.uni WD_%=;\n bra.uni WL_%=;\nWD_%=:\n}"                     \
            :: "r"(_m), "r"(_p) : "memory");                                      \
    }                                                                             \
} while (0)

#define TCGEN05_ALLOC_CG2(smem_addr, ncols) \
    asm volatile("tcgen05.alloc.cta_group::2.sync.aligned.shared::cta.b32 [%0], %1;" \
                 :: "r"(smem_addr), "r"(ncols) : "memory")
#define TCGEN05_RELINQ_CG2() \
    asm volatile("tcgen05.relinquish_alloc_permit.cta_group::2.sync.aligned;")
#define TCGEN05_DEALLOC_CG2(tmem, ncols) \
    asm volatile("tcgen05.dealloc.cta_group::2.sync.aligned.b32 %0, %1;" :: "r"(tmem), "r"(ncols))
#define TCGEN05_COMMIT_MC_CG2(mbar, mask) \
    asm volatile("tcgen05.commit.cta_group::2.mbarrier::arrive::one.shared::cluster.multicast::cluster.b64 [%0], %1;" \
                 :: "r"(mbar), "h"((uint16_t)(mask)) : "memory")
#define TCGEN05_FENCE_AFTER() \
    asm volatile("tcgen05.fence::after_thread_sync;" ::: "memory")
#define TCGEN05_WAIT_LD() \
    asm volatile("tcgen05.wait::ld.sync.aligned;" ::: "memory")
#define FENCE_PROXY_ASYNC() \
    asm volatile("fence.proxy.async.shared::cta;" ::: "memory")
#define CLUSTER_SYNC() do { \
    asm volatile("barrier.cluster.arrive.aligned;" ::: "memory"); \
    asm volatile("barrier.cluster.wait.aligned;" ::: "memory"); \
} while (0)

#define CP_BULK_G2S(dst, src, bytes, mbar) \
    asm volatile("cp.async.bulk.shared::cluster.global.mbarrier::complete_tx::bytes " \
                 "[%0], [%1], %2, [%3];" \
                 :: "r"(dst), "l"(src), "r"(bytes), "r"(mbar) : "memory")

#define TCGEN05_LD_X32(r, tmem_addr)                                              \
    asm volatile("tcgen05.ld.sync.aligned.32x32b.x32.b32 "                        \
        "{%0, %1, %2, %3, %4, %5, %6, %7, "                                       \
        " %8, %9, %10, %11, %12, %13, %14, %15, "                                 \
        " %16, %17, %18, %19, %20, %21, %22, %23, "                               \
        " %24, %25, %26, %27, %28, %29, %30, %31}, [%32];"                        \
        : "=r"((r)[0]),  "=r"((r)[1]),  "=r"((r)[2]),  "=r"((r)[3]),              \
          "=r"((r)[4]),  "=r"((r)[5]),  "=r"((r)[6]),  "=r"((r)[7]),              \
          "=r"((r)[8]),  "=r"((r)[9]),  "=r"((r)[10]), "=r"((r)[11]),             \
          "=r"((r)[12]), "=r"((r)[13]), "=r"((r)[14]), "=r"((r)[15]),             \
          "=r"((r)[16]), "=r"((r)[17]), "=r"((r)[18]), "=r"((r)[19]),             \
          "=r"((r)[20]), "=r"((r)[21]), "=r"((r)[22]), "=r"((r)[23]),             \
          "=r"((r)[24]), "=r"((r)[25]), "=r"((r)[26]), "=r"((r)[27]),             \
          "=r"((r)[28]), "=r"((r)[29]), "=r"((r)[30]), "=r"((r)[31])              \
        : "r"(tmem_addr))

// cta_group::2 bf16 SS MMA (M=256 across the pair; A and B split per CTA)
__device__ __forceinline__ void mma_bf16_ss_cg2(uint32_t d_tmem, uint64_t a_desc,
                                                uint64_t b_desc, uint32_t idesc,
                                                uint32_t enable_acc) {
    asm volatile("{\n .reg .pred p;\n setp.ne.u32 p, %5, 0;\n"
        " tcgen05.mma.cta_group::2.kind::f16 [%0], %1, %2, %3, "
        "{%4, %4, %4, %4, %4, %4, %4, %4}, p;\n}"
        :: "r"(d_tmem), "l"(a_desc), "l"(b_desc), "r"(idesc), "r"(0u), "r"(enable_acc)
        : "memory");
}

// SW64 K-major descriptor: layout=4, version=1, SBO=32, LBO=1
__device__ __forceinline__ uint64_t make_desc_sw64(uint32_t base_addr) {
    const uint64_t BASE = (uint64_t(4) << 61) | (uint64_t(1) << 46) |
                          (uint64_t(32) << 32) | (uint64_t(1) << 16);
    return BASE | ((uint64_t)(base_addr >> 4) & 0x3FFF);
}

#endif // HAS_TCGEN05

// ======================= kernel 0: segment starts =======================
__global__ void __launch_bounds__(256) segstart_kernel(const int* __restrict__ segment_ids) {
    const int t = blockIdx.x * blockDim.x + threadIdx.x;
    if (t >= NTOK) return;
    const int cur = __ldg(segment_ids + t);
    if (t == 0) {
        for (int s = 0; s <= cur; s++) g_segstart[s] = 0;
    } else {
        const int prev = __ldg(segment_ids + t - 1);
        for (int s = prev + 1; s <= cur; s++) g_segstart[s] = t;
    }
    if (t == NTOK - 1) {
        for (int s = cur + 1; s <= NSLOT; s++) g_segstart[s] = NTOK;
    }
}

// ======================= kernel 1: embed + pool + LN (tiled swizzled store) ===
__global__ void __launch_bounds__(192) embed_ln_kernel(
    const int*   __restrict__ token_ids,
    const int*   __restrict__ section_ids,
    const int*   __restrict__ temporality_ids,
    const int*   __restrict__ negation_ids,
    const int*   __restrict__ position_ids,
    const int*   __restrict__ timestamp_ids,
    const float* __restrict__ token_table,
    const float* __restrict__ section_table,
    const float* __restrict__ temporality_table,
    const float* __restrict__ negation_table,
    const float* __restrict__ position_table,
    const float* __restrict__ timestamp_table,
    const float* __restrict__ ln_gamma,
    const float* __restrict__ ln_beta)
{
    const int slot = blockIdx.x;
    const int tid  = threadIdx.x;   // 0..191

    const int lo  = __ldg(g_segstart + slot);
    const int hi  = __ldg(g_segstart + slot + 1);
    const int cnt = hi - lo;

    float4 a0 = {0.f,0.f,0.f,0.f}, a1 = {0.f,0.f,0.f,0.f};
    float4 a2 = {0.f,0.f,0.f,0.f}, a3 = {0.f,0.f,0.f,0.f};

    int t = lo;
    for (; t + 8 <= hi; t += 8) {
        int tk[8];
        #pragma unroll
        for (int j = 0; j < 8; j++) tk[j] = __ldg(token_ids + t + j);
        float4 v[8];
        #pragma unroll
        for (int j = 0; j < 8; j++)
            v[j] = __ldg((const float4*)(token_table + (size_t)tk[j] * DDIM) + tid);
        a0.x += v[0].x + v[4].x; a0.y += v[0].y + v[4].y; a0.z += v[0].z + v[4].z; a0.w += v[0].w + v[4].w;
        a1.x += v[1].x + v[5].x; a1.y += v[1].y + v[5].y; a1.z += v[1].z + v[5].z; a1.w += v[1].w + v[5].w;
        a2.x += v[2].x + v[6].x; a2.y += v[2].y + v[6].y; a2.z += v[2].z + v[6].z; a2.w += v[2].w + v[6].w;
        a3.x += v[3].x + v[7].x; a3.y += v[3].y + v[7].y; a3.z += v[3].z + v[7].z; a3.w += v[3].w + v[7].w;
    }
    for (; t + 4 <= hi; t += 4) {
        int tk[4];
        #pragma unroll
        for (int j = 0; j < 4; j++) tk[j] = __ldg(token_ids + t + j);
        float4 v[4];
        #pragma unroll
        for (int j = 0; j < 4; j++)
            v[j] = __ldg((const float4*)(token_table + (size_t)tk[j] * DDIM) + tid);
        a0.x += v[0].x; a0.y += v[0].y; a0.z += v[0].z; a0.w += v[0].w;
        a1.x += v[1].x; a1.y += v[1].y; a1.z += v[1].z; a1.w += v[1].w;
        a2.x += v[2].x; a2.y += v[2].y; a2.z += v[2].z; a2.w += v[2].w;
        a3.x += v[3].x; a3.y += v[3].y; a3.z += v[3].z; a3.w += v[3].w;
    }
    for (; t < hi; t++) {
        const int tok = __ldg(token_ids + t);
        const float4 v = __ldg((const float4*)(token_table + (size_t)tok * DDIM) + tid);
        a0.x += v.x; a0.y += v.y; a0.z += v.z; a0.w += v.w;
    }
    float ax = (a0.x + a1.x) + (a2.x + a3.x);
    float ay = (a0.y + a1.y) + (a2.y + a3.y);
    float az = (a0.z + a1.z) + (a2.z + a3.z);
    float aw = (a0.w + a1.w) + (a2.w + a3.w);

    const float inv = 1.0f / fmaxf((float)cnt, 1.0f);
    ax *= inv; ay *= inv; az *= inv; aw *= inv;

    {
        const int id = __ldg(section_ids + slot);
        const float4 v = __ldg((const float4*)(section_table + (size_t)id * DDIM) + tid);
        ax += v.x; ay += v.y; az += v.z; aw += v.w;
    }
    {
        const int id = __ldg(temporality_ids + slot);
        const float4 v = __ldg((const float4*)(temporality_table + (size_t)id * DDIM) + tid);
        ax += v.x; ay += v.y; az += v.z; aw += v.w;
    }
    {
        const int id = __ldg(negation_ids + slot);
        const float4 v = __ldg((const float4*)(negation_table + (size_t)id * DDIM) + tid);
        ax += v.x; ay += v.y; az += v.z; aw += v.w;
    }
    {
        const int id = __ldg(position_ids + slot);
        const float4 v = __ldg((const float4*)(position_table + (size_t)id * DDIM) + tid);
        ax += v.x; ay += v.y; az += v.z; aw += v.w;
    }
    {
        const int id = __ldg(timestamp_ids + slot);
        const float4 v = __ldg((const float4*)(timestamp_table + (size_t)id * DDIM) + tid);
        ax += v.x; ay += v.y; az += v.z; aw += v.w;
    }

    float s  = ax + ay + az + aw;
    float ss = ax * ax + ay * ay + az * az + aw * aw;
    #pragma unroll
    for (int o = 16; o > 0; o >>= 1) {
        s  += __shfl_down_sync(0xffffffffu, s,  o);
        ss += __shfl_down_sync(0xffffffffu, ss, o);
    }

    __shared__ float red_s[6], red_ss[6], stat[2];
    const int warp = tid >> 5, lane = tid & 31;
    if (lane == 0) { red_s[warp] = s; red_ss[warp] = ss; }
    __syncthreads();
    if (tid == 0) {
        float S = 0.f, SS = 0.f;
        #pragma unroll
        for (int i = 0; i < 6; i++) { S += red_s[i]; SS += red_ss[i]; }
        const float mean = S * (1.0f / DDIM);
        const float var  = SS * (1.0f / DDIM) - mean * mean;
        stat[0] = mean;
        stat[1] = rsqrtf(var + LN_EPS);
    }
    __syncthreads();
    const float mean = stat[0], rstd = stat[1];

    const float4 g = __ldg((const float4*)ln_gamma + tid);
    const float4 b = __ldg((const float4*)ln_beta  + tid);
    float ox = (ax - mean) * rstd * g.x + b.x;
    float oy = (ay - mean) * rstd * g.y + b.y;
    float oz = (az - mean) * rstd * g.z + b.z;
    float ow = (aw - mean) * rstd * g.w + b.w;

    __nv_bfloat16 hx = __float2bfloat16_rn(ox), hy = __float2bfloat16_rn(oy);
    __nv_bfloat16 hz = __float2bfloat16_rn(oz), hw = __float2bfloat16_rn(ow);
    __nv_bfloat16 lx = __float2bfloat16_rn(ox - __bfloat162float(hx));
    __nv_bfloat16 ly = __float2bfloat16_rn(oy - __bfloat162float(hy));
    __nv_bfloat16 lz = __float2bfloat16_rn(oz - __bfloat162float(hz));
    __nv_bfloat16 lw = __float2bfloat16_rn(ow - __bfloat162float(hw));

    // 128-row tile, SW64 pre-swizzled store.
    const int tile  = slot >> 7;
    const int row   = slot & 127;
    const int chunk = tid >> 3;
    const int inner = (tid & 7) * 8;
    const uint32_t swoff = sw64((uint32_t)(row * 64 + (inner & 48))) + (inner & 8);
    const size_t tile_off = (size_t)(tile * NCHUNK + chunk) * SZ_T + swoff;

    uint2 hv, lv;
    ((__nv_bfloat162*)&hv)[0] = __halves2bfloat162(hx, hy);
    ((__nv_bfloat162*)&hv)[1] = __halves2bfloat162(hz, hw);
    ((__nv_bfloat162*)&lv)[0] = __halves2bfloat162(lx, ly);
    ((__nv_bfloat162*)&lv)[1] = __halves2bfloat162(lz, lw);
    *(uint2*)((char*)g_ahi + tile_off) = hv;
    *(uint2*)((char*)g_alo + tile_off) = lv;
}

// ======================= kernel 2: split proj_w (128-row tiles, swizzled) =====
__global__ void __launch_bounds__(256) wsplit_kernel(const float* __restrict__ W) {
    const int i = blockIdx.x * blockDim.x + threadIdx.x;   // float4 index
    const float4 v = __ldg((const float4*)W + i);
    __nv_bfloat16 hx = __float2bfloat16_rn(v.x), hy = __float2bfloat16_rn(v.y);
    __nv_bfloat16 hz = __float2bfloat16_rn(v.z), hw = __float2bfloat16_rn(v.w);
    __nv_bfloat16 lx = __float2bfloat16_rn(v.x - __bfloat162float(hx));
    __nv_bfloat16 ly = __float2bfloat16_rn(v.y - __bfloat162float(hy));
    __nv_bfloat16 lz = __float2bfloat16_rn(v.z - __bfloat162float(hz));
    __nv_bfloat16 lw = __float2bfloat16_rn(v.w - __bfloat162float(hw));

    const int row   = i / (DDIM / 4);           // 0..767 (output feature)
    const int col4  = i % (DDIM / 4);
    const int chunk = col4 >> 3;
    const int inner = (col4 & 7) * 8;
    const int tile  = row >> 7;                 // 0..5
    const int lrow  = row & 127;
    const uint32_t swoff = sw64((uint32_t)(lrow * 64 + (inner & 48))) + (inner & 8);
    const size_t tile_off = (size_t)(tile * NCHUNK + chunk) * SZ_T + swoff;

    uint2 hv, lv;
    ((__nv_bfloat162*)&hv)[0] = __halves2bfloat162(hx, hy);
    ((__nv_bfloat162*)&hv)[1] = __halves2bfloat162(hz, hw);
    ((__nv_bfloat162*)&lv)[0] = __halves2bfloat162(lx, ly);
    ((__nv_bfloat162*)&lv)[1] = __halves2bfloat162(lz, lw);
    *(uint2*)((char*)g_whi + tile_off) = hv;
    *(uint2*)((char*)g_wlo + tile_off) = lv;
}

// ======================= kernel 3: cta_group::2 tcgen05 GEMM ==================
#define OFF_TM   0
#define OFF_FULL 16                    // 4 full barriers
#define OFF_MMA  48                    // 4 mma barriers
#define OFF_DATA 1024
#define GEMM_SMEM (OFF_DATA + NBUF*SZ_BUF)   // 132096

__global__ void __launch_bounds__(256, 1)
#if HAS_TCGEN05
__cluster_dims__(2, 1, 1)
#endif
gemm_tc_kernel(const float* __restrict__ bias, float* __restrict__ C,
               int tail_start, int total_out)
{
#if HAS_TCGEN05
    extern __shared__ char smem[];
    const uint32_t sb  = smem_u32(smem);
    const int tid  = threadIdx.x;
    const uint32_t rank = cluster_rank();        // 0 = leader
    const int bn   = blockIdx.x >> 1;            // 0..2
    const int bm   = blockIdx.y;                 // 0..15

    if (blockIdx.x == 0 && bm == 0) {
        for (int i = tail_start + tid; i < total_out; i += 256) C[i] = 0.0f;
    }

    if (tid < 32) {
        TCGEN05_ALLOC_CG2(sb + OFF_TM, 256);
        TCGEN05_RELINQ_CG2();
    }
    if (tid == 0) {
        #pragma unroll
        for (int i = 0; i < NBUF; i++) {
            // leader full barrier: own expect_tx arrive + follower remote arrive
            MBARRIER_INIT(sb + OFF_FULL + i * 8, rank == 0 ? 2u : 1u);
            MBARRIER_INIT(sb + OFF_MMA  + i * 8, 1u);
        }
        FENCE_PROXY_ASYNC();
    }
    __syncthreads();
    uint32_t tmem;
    asm volatile("ld.shared.b32 %0, [%1];" : "=r"(tmem) : "r"(sb + OFF_TM));

    CLUSTER_SYNC();   // barriers visible cluster-wide before remote arrivals

    if (tid == 0) {
        // Each CTA supplies its own M-half of A and N-half of B.
        const int tA = bm * 2 + (int)rank;       // 128-row A tile index
        const int tW = bn * 2 + (int)rank;       // 128-row W tile index
        const char* aH = (const char*)g_ahi + (size_t)tA * NCHUNK * SZ_T;
        const char* aL = (const char*)g_alo + (size_t)tA * NCHUNK * SZ_T;
        const char* bH = (const char*)g_whi + (size_t)tW * NCHUNK * SZ_T;
        const char* bL = (const char*)g_wlo + (size_t)tW * NCHUNK * SZ_T;

        auto load_chunk = [&](int c) {
            const int buf = c & (NBUF - 1);
            const uint32_t base = sb + OFF_DATA + buf * SZ_BUF;
            const uint32_t fm   = sb + OFF_FULL + buf * 8;
            MBARRIER_EXPECT_TX(fm, SZ_BUF);      // own 32 KB
            CP_BULK_G2S(base,            aH + (size_t)c * SZ_T, SZ_T, fm);
            CP_BULK_G2S(base + SZ_T,     aL + (size_t)c * SZ_T, SZ_T, fm);
            CP_BULK_G2S(base + 2*SZ_T,   bH + (size_t)c * SZ_T, SZ_T, fm);
            CP_BULK_G2S(base + 3*SZ_T,   bL + (size_t)c * SZ_T, SZ_T, fm);
        };

        load_chunk(0);
        load_chunk(1);
        load_chunk(2);

        // idesc: F32 accum, BF16xBF16, N=256, M=256 (cg2)
        const uint32_t idesc = (1u << 4) | (1u << 7) | (1u << 10) |
                               (32u << 17) | (16u << 24);

        if (rank == 0) {
            for (int c = 0; c < NCHUNK; c++) {
                const int buf = c & (NBUF - 1);
                // both halves resident (own tx + follower arrive)
                MBARRIER_WAIT_PARITY(sb + OFF_FULL + buf * 8, (uint32_t)((c >> 2) & 1));

                const uint32_t base = sb + OFF_DATA + buf * SZ_BUF;
                const uint64_t dAH = make_desc_sw64(base);
                const uint64_t dAL = make_desc_sw64(base + SZ_T);
                const uint64_t dBH = make_desc_sw64(base + 2 * SZ_T);
                const uint64_t dBL = make_desc_sw64(base + 3 * SZ_T);
                #pragma unroll
                for (int ks = 0; ks < 2; ks++) {
                    const uint64_t o = ks * 2;
                    mma_bf16_ss_cg2(tmem, dAH + o, dBH + o, idesc, (c | ks) != 0);
                    mma_bf16_ss_cg2(tmem, dAH + o, dBL + o, idesc, 1u);
                    mma_bf16_ss_cg2(tmem, dAL + o, dBH + o, idesc, 1u);
                }
                TCGEN05_COMMIT_MC_CG2(sb + OFF_MMA + buf * 8, 0x3);

                if (c + LEAD < NCHUNK) {
                    const int cc = c + LEAD - NBUF;   // previous occupant
                    if (cc >= 0) {
                        MBARRIER_WAIT_PARITY(sb + OFF_MMA + (cc & (NBUF - 1)) * 8,
                                             (uint32_t)((cc >> 2) & 1));
                    }
                    load_chunk(c + LEAD);
                }
            }
        } else {
            // follower: signal data-ready to leader; pace loads on MMA commits
            for (int c = 0; c < NCHUNK; c++) {
                const int buf = c & (NBUF - 1);
                MBARRIER_WAIT_PARITY(sb + OFF_FULL + buf * 8, (uint32_t)((c >> 2) & 1));
                MBARRIER_ARRIVE_RANK0(sb + OFF_FULL + buf * 8);

                if (c + LEAD < NCHUNK) {
                    const int cc = c + LEAD - NBUF;
                    if (cc >= 0) {
                        MBARRIER_WAIT_PARITY(sb + OFF_MMA + (cc & (NBUF - 1)) * 8,
                                             (uint32_t)((cc >> 2) & 1));
                    }
                    load_chunk(c + LEAD);
                }
            }
        }
        // final MMA completion (commit multicast lands on both CTAs)
        const int cl = NCHUNK - 1;
        MBARRIER_WAIT_PARITY(sb + OFF_MMA + (cl & (NBUF - 1)) * 8,
                             (uint32_t)((cl >> 2) & 1));
    }

    __syncthreads();
    TCGEN05_FENCE_AFTER();

    // -------- epilogue: each CTA writes its own M-half (128 rows x 256 cols) --
    const int w    = tid >> 5, lane = tid & 31;
    const int part = w & 3,    half = w >> 2;
    const int row  = bm * 256 + (int)rank * 128 + part * 32 + lane;
    float* crow = C + (size_t)row * DDIM;

    #pragma unroll
    for (int pair = 0; pair < 2; pair++) {
        const int colbase = half * 128 + pair * 64;
        uint32_t r0[32], r1[32];
        TCGEN05_LD_X32(r0, tmem + colbase);
        TCGEN05_LD_X32(r1, tmem + colbase + 32);
        TCGEN05_WAIT_LD();
        const int gcol0 = bn * 256 + colbase;
        #pragma unroll
        for (int i = 0; i < 32; i += 4) {
            const float4 bv = __ldg((const float4*)(bias + gcol0 + i));
            float4 o;
            o.x = __uint_as_float(r0[i + 0]) + bv.x;
            o.y = __uint_as_float(r0[i + 1]) + bv.y;
            o.z = __uint_as_float(r0[i + 2]) + bv.z;
            o.w = __uint_as_float(r0[i + 3]) + bv.w;
            *(float4*)(crow + gcol0 + i) = o;
        }
        #pragma unroll
        for (int i = 0; i < 32; i += 4) {
            const float4 bv = __ldg((const float4*)(bias + gcol0 + 32 + i));
            float4 o;
            o.x = __uint_as_float(r1[i + 0]) + bv.x;
            o.y = __uint_as_float(r1[i + 1]) + bv.y;
            o.z = __uint_as_float(r1[i + 2]) + bv.z;
            o.w = __uint_as_float(r1[i + 3]) + bv.w;
            *(float4*)(crow + gcol0 + 32 + i) = o;
        }
    }

    __syncthreads();
    if (tid < 32) TCGEN05_DEALLOC_CG2(tmem, 256);
    CLUSTER_SYNC();   // no CTA exits while peer may still touch its SMEM
#endif // HAS_TCGEN05
}

// ======================= launch =======================
extern "C" void kernel_launch(void* const* d_in, const int* in_sizes, int n_in,
                              void* d_out, int out_size) {
    const int*   token_ids         = (const int*)  d_in[0];
    const int*   segment_ids       = (const int*)  d_in[1];
    const int*   section_ids       = (const int*)  d_in[2];
    const int*   temporality_ids   = (const int*)  d_in[3];
    const int*   negation_ids      = (const int*)  d_in[4];
    const int*   position_ids      = (const int*)  d_in[5];
    const int*   timestamp_ids     = (const int*)  d_in[6];
    const float* token_table       = (const float*)d_in[7];
    const float* section_table     = (const float*)d_in[8];
    const float* temporality_table = (const float*)d_in[9];
    const float* negation_table    = (const float*)d_in[10];
    const float* position_table    = (const float*)d_in[11];
    const float* timestamp_table   = (const float*)d_in[12];
    const float* ln_gamma          = (const float*)d_in[13];
    const float* ln_beta           = (const float*)d_in[14];
    const float* proj_w            = (const float*)d_in[15];
    const float* proj_b            = (const float*)d_in[16];

    float* out = (float*)d_out;

    cudaFuncSetAttribute(gemm_tc_kernel,
                         cudaFuncAttributeMaxDynamicSharedMemorySize, GEMM_SMEM);

    segstart_kernel<<<NTOK / 256, 256>>>(segment_ids);

    wsplit_kernel<<<(DDIM * DDIM / 4) / 256, 256>>>(proj_w);

    embed_ln_kernel<<<NSLOT, 192>>>(
        token_ids, section_ids, temporality_ids, negation_ids,
        position_ids, timestamp_ids, token_table, section_table,
        temporality_table, negation_table, position_table, timestamp_table,
        ln_gamma, ln_beta);

    // 48 clusters of 2 CTAs: cluster tile M=256 x N=256
    dim3 grid_tc(6, 16);
    gemm_tc_kernel<<<grid_tc, 256, GEMM_SMEM>>>(proj_b, out,
                                                NSLOT * DDIM, out_size);
}

// round 14
// speedup vs baseline: 1.0354x; 1.0354x over previous
#include <cuda_runtime.h>
#include <cuda_bf16.h>
#include <cstdint>

#define NTOK   65536
#define NSLOT  4096
#define DDIM   768
#define LN_EPS 1e-5f

// GEMM tiling: cg1, tile M=128 x N=256, K-chunks of 32.
// hi/lo are K-interleaved inside one SW128 tile: row = 64 bf16 = 128 B,
// elements 0..31 = hi of the chunk's 32 k-values, 32..63 = lo.
#define KCH     32
#define NCHUNK  (DDIM / KCH)           // 24
#define NBUF    4
#define LEAD    3
#define SZ_TA   (128 * 128)            // 16384 B: A tile (hi+lo) per chunk
#define SZ_TB   (256 * 128)            // 32768 B: W tile (hi+lo) per chunk
#define SZ_BUF  (SZ_TA + SZ_TB)        // 49152

// ---- tcgen05 capability gate (per device-compile pass) ----
#if (defined(__CUDA_ARCH_SPECIFIC__) && (__CUDA_ARCH_SPECIFIC__ >= 1000)) || \
    (defined(__CUDA_ARCH_FAMILY_SPECIFIC__) && (__CUDA_ARCH_FAMILY_SPECIFIC__ >= 1000)) || \
    defined(__CUDA_ARCH_FEAT_SM100_ALL) || defined(__CUDA_ARCH_FEAT_SM101_ALL) || \
    defined(__CUDA_ARCH_FEAT_SM103_ALL)
#define HAS_TCGEN05 1
#else
#define HAS_TCGEN05 0
#endif

// ---------------- device scratch (SW128 tiles, hi/lo K-interleaved) ----------------
// A: tile (bm, c) at (bm*NCHUNK + c)*SZ_TA. 32 bm-tiles of 128 rows.
__device__ __align__(1024) __nv_bfloat16 g_a[(size_t)NSLOT * DDIM * 2];
// W: tile (bn, c) at (bn*NCHUNK + c)*SZ_TB. 3 bn-tiles of 256 rows.
__device__ __align__(1024) __nv_bfloat16 g_w[(size_t)DDIM * DDIM * 2];
__device__ int g_segstart[NSLOT + 1];

// ---------------- PTX helpers ----------------
__device__ __forceinline__ uint32_t smem_u32(const void* p) {
    uint32_t a;
    asm("{ .reg .u64 t; cvta.to.shared.u64 t, %1; cvt.u32.u64 %0, t; }" : "=r"(a) : "l"(p));
    return a;
}

// SW128 swizzle; valid to apply directly to 8B-aligned offsets.
__device__ __forceinline__ uint32_t sw128(uint32_t off) {
    return off ^ ((off >> 3) & 0x70);
}

#if HAS_TCGEN05

#define MBARRIER_INIT(addr, cnt) \
    asm volatile("mbarrier.init.shared.b64 [%0], %1;" :: "r"(addr), "r"(cnt) : "memory")

#define MBARRIER_EXPECT_TX(addr, bytes) \
    asm volatile("mbarrier.arrive.expect_tx.shared.b64 _, [%0], %1;" \
                 :: "r"(addr), "r"(bytes) : "memory")

#define MBARRIER_WAIT_PARITY(mbar, parity) do {                                   \
    uint32_t _m = (mbar); uint32_t _p = (parity); uint32_t _done;                 \
    asm volatile("{\n .reg .pred p;\n"                                            \
        " mbarrier.try_wait.parity.acquire.cta.shared::cta.b64 p, [%1], %2;\n"    \
        " selp.b32 %0, 1, 0, p;\n}"                                               \
        : "=r"(_done) : "r"(_m), "r"(_p) : "memory");                             \
    if (!_done) {                                                                 \
        asm volatile("{\n .reg .pred P1;\n"                                       \
            "WL_%=:\n"                                                            \
            " mbarrier.try_wait.parity.acquire.cta.shared::cta.b64 P1, [%0], %1, 0x989680;\n" \
            " @P1 bra.uni WD_%=;\n bra.uni WL_%=;\nWD_%=:\n}"                     \
            :: "r"(_m), "r"(_p) : "memory");                                      \
    }                                                                             \
} while (0)

#define TCGEN05_ALLOC(smem_addr, ncols) \
    asm volatile("tcgen05.alloc.cta_group::1.sync.aligned.shared::cta.b32 [%0], %1;" \
                 :: "r"(smem_addr), "r"(ncols) : "memory")
#define TCGEN05_RELINQ() \
    asm volatile("tcgen05.relinquish_alloc_permit.cta_group::1.sync.aligned;")
#define TCGEN05_DEALLOC(tmem, ncols) \
    asm volatile("tcgen05.dealloc.cta_group::1.sync.aligned.b32 %0, %1;" :: "r"(tmem), "r"(ncols))
#define TCGEN05_COMMIT(mbar) \
    asm volatile("tcgen05.commit.cta_group::1.mbarrier::arrive::one.shared::cluster.b64 [%0];" \
                 :: "r"(mbar) : "memory")
#define TCGEN05_FENCE_AFTER() \
    asm volatile("tcgen05.fence::after_thread_sync;" ::: "memory")
#define TCGEN05_WAIT_LD() \
    asm volatile("tcgen05.wait::ld.sync.aligned;" ::: "memory")
#define FENCE_PROXY_ASYNC() \
    asm volatile("fence.proxy.async.shared::cta;" ::: "memory")

#define CP_BULK_G2S(dst, src, bytes, mbar) \
    asm volatile("cp.async.bulk.shared::cluster.global.mbarrier::complete_tx::bytes " \
                 "[%0], [%1], %2, [%3];" \
                 :: "r"(dst), "l"(src), "r"(bytes), "r"(mbar) : "memory")

#define TCGEN05_LD_X32(r, tmem_addr)                                              \
    asm volatile("tcgen05.ld.sync.aligned.32x32b.x32.b32 "                        \
        "{%0, %1, %2, %3, %4, %5, %6, %7, "                                       \
        " %8, %9, %10, %11, %12, %13, %14, %15, "                                 \
        " %16, %17, %18, %19, %20, %21, %22, %23, "                               \
        " %24, %25, %26, %27, %28, %29, %30, %31}, [%32];"                        \
        : "=r"((r)[0]),  "=r"((r)[1]),  "=r"((r)[2]),  "=r"((r)[3]),              \
          "=r"((r)[4]),  "=r"((r)[5]),  "=r"((r)[6]),  "=r"((r)[7]),              \
          "=r"((r)[8]),  "=r"((r)[9]),  "=r"((r)[10]), "=r"((r)[11]),             \
          "=r"((r)[12]), "=r"((r)[13]), "=r"((r)[14]), "=r"((r)[15]),             \
          "=r"((r)[16]), "=r"((r)[17]), "=r"((r)[18]), "=r"((r)[19]),             \
          "=r"((r)[20]), "=r"((r)[21]), "=r"((r)[22]), "=r"((r)[23]),             \
          "=r"((r)[24]), "=r"((r)[25]), "=r"((r)[26]), "=r"((r)[27]),             \
          "=r"((r)[28]), "=r"((r)[29]), "=r"((r)[30]), "=r"((r)[31])              \
        : "r"(tmem_addr))

__device__ __forceinline__ void mma_bf16_ss(uint32_t d_tmem, uint64_t a_desc,
                                            uint64_t b_desc, uint32_t idesc,
                                            uint32_t enable_acc) {
    asm volatile("{\n .reg .pred p;\n setp.ne.u32 p, %5, 0;\n"
        " tcgen05.mma.cta_group::1.kind::f16 [%0], %1, %2, %3, {%4, %4, %4, %4}, p;\n}"
        :: "r"(d_tmem), "l"(a_desc), "l"(b_desc), "r"(idesc), "r"(0u), "r"(enable_acc)
        : "memory");
}

// SW128 K-major descriptor: layout=2, version=1, SBO=64, LBO=1 (verified in r5)
__device__ __forceinline__ uint64_t make_desc_sw128(uint32_t base_addr) {
    const uint64_t BASE = (uint64_t(2) << 61) | (uint64_t(1) << 46) |
                          (uint64_t(64) << 32) | (uint64_t(1) << 16);
    return BASE | ((uint64_t)(base_addr >> 4) & 0x3FFF);
}

#endif // HAS_TCGEN05

// ======================= kernel 0: segment starts =======================
__global__ void __launch_bounds__(256) segstart_kernel(const int* __restrict__ segment_ids) {
    const int t = blockIdx.x * blockDim.x + threadIdx.x;
    if (t >= NTOK) return;
    const int cur = __ldg(segment_ids + t);
    if (t == 0) {
        for (int s = 0; s <= cur; s++) g_segstart[s] = 0;
    } else {
        const int prev = __ldg(segment_ids + t - 1);
        for (int s = prev + 1; s <= cur; s++) g_segstart[s] = t;
    }
    if (t == NTOK - 1) {
        for (int s = cur + 1; s <= NSLOT; s++) g_segstart[s] = NTOK;
    }
}

// ======================= kernel 1: embed + pool + LN =======================
__global__ void __launch_bounds__(192) embed_ln_kernel(
    const int*   __restrict__ token_ids,
    const int*   __restrict__ section_ids,
    const int*   __restrict__ temporality_ids,
    const int*   __restrict__ negation_ids,
    const int*   __restrict__ position_ids,
    const int*   __restrict__ timestamp_ids,
    const float* __restrict__ token_table,
    const float* __restrict__ section_table,
    const float* __restrict__ temporality_table,
    const float* __restrict__ negation_table,
    const float* __restrict__ position_table,
    const float* __restrict__ timestamp_table,
    const float* __restrict__ ln_gamma,
    const float* __restrict__ ln_beta)
{
    const int slot = blockIdx.x;
    const int tid  = threadIdx.x;   // 0..191

    const int lo  = __ldg(g_segstart + slot);
    const int hi  = __ldg(g_segstart + slot + 1);
    const int cnt = hi - lo;

    float4 a0 = {0.f,0.f,0.f,0.f}, a1 = {0.f,0.f,0.f,0.f};
    float4 a2 = {0.f,0.f,0.f,0.f}, a3 = {0.f,0.f,0.f,0.f};

    int t = lo;
    for (; t + 8 <= hi; t += 8) {
        int tk[8];
        #pragma unroll
        for (int j = 0; j < 8; j++) tk[j] = __ldg(token_ids + t + j);
        float4 v[8];
        #pragma unroll
        for (int j = 0; j < 8; j++)
            v[j] = __ldg((const float4*)(token_table + (size_t)tk[j] * DDIM) + tid);
        a0.x += v[0].x + v[4].x; a0.y += v[0].y + v[4].y; a0.z += v[0].z + v[4].z; a0.w += v[0].w + v[4].w;
        a1.x += v[1].x + v[5].x; a1.y += v[1].y + v[5].y; a1.z += v[1].z + v[5].z; a1.w += v[1].w + v[5].w;
        a2.x += v[2].x + v[6].x; a2.y += v[2].y + v[6].y; a2.z += v[2].z + v[6].z; a2.w += v[2].w + v[6].w;
        a3.x += v[3].x + v[7].x; a3.y += v[3].y + v[7].y; a3.z += v[3].z + v[7].z; a3.w += v[3].w + v[7].w;
    }
    for (; t + 4 <= hi; t += 4) {
        int tk[4];
        #pragma unroll
        for (int j = 0; j < 4; j++) tk[j] = __ldg(token_ids + t + j);
        float4 v[4];
        #pragma unroll
        for (int j = 0; j < 4; j++)
            v[j] = __ldg((const float4*)(token_table + (size_t)tk[j] * DDIM) + tid);
        a0.x += v[0].x; a0.y += v[0].y; a0.z += v[0].z; a0.w += v[0].w;
        a1.x += v[1].x; a1.y += v[1].y; a1.z += v[1].z; a1.w += v[1].w;
        a2.x += v[2].x; a2.y += v[2].y; a2.z += v[2].z; a2.w += v[2].w;
        a3.x += v[3].x; a3.y += v[3].y; a3.z += v[3].z; a3.w += v[3].w;
    }
    for (; t < hi; t++) {
        const int tok = __ldg(token_ids + t);
        const float4 v = __ldg((const float4*)(token_table + (size_t)tok * DDIM) + tid);
        a0.x += v.x; a0.y += v.y; a0.z += v.z; a0.w += v.w;
    }
    float ax = (a0.x + a1.x) + (a2.x + a3.x);
    float ay = (a0.y + a1.y) + (a2.y + a3.y);
    float az = (a0.z + a1.z) + (a2.z + a3.z);
    float aw = (a0.w + a1.w) + (a2.w + a3.w);

    const float inv = 1.0f / fmaxf((float)cnt, 1.0f);
    ax *= inv; ay *= inv; az *= inv; aw *= inv;

    {
        const int id = __ldg(section_ids + slot);
        const float4 v = __ldg((const float4*)(section_table + (size_t)id * DDIM) + tid);
        ax += v.x; ay += v.y; az += v.z; aw += v.w;
    }
    {
        const int id = __ldg(temporality_ids + slot);
        const float4 v = __ldg((const float4*)(temporality_table + (size_t)id * DDIM) + tid);
        ax += v.x; ay += v.y; az += v.z; aw += v.w;
    }
    {
        const int id = __ldg(negation_ids + slot);
        const float4 v = __ldg((const float4*)(negation_table + (size_t)id * DDIM) + tid);
        ax += v.x; ay += v.y; az += v.z; aw += v.w;
    }
    {
        const int id = __ldg(position_ids + slot);
        const float4 v = __ldg((const float4*)(position_table + (size_t)id * DDIM) + tid);
        ax += v.x; ay += v.y; az += v.z; aw += v.w;
    }
    {
        const int id = __ldg(timestamp_ids + slot);
        const float4 v = __ldg((const float4*)(timestamp_table + (size_t)id * DDIM) + tid);
        ax += v.x; ay += v.y; az += v.z; aw += v.w;
    }

    float s  = ax + ay + az + aw;
    float ss = ax * ax + ay * ay + az * az + aw * aw;
    #pragma unroll
    for (int o = 16; o > 0; o >>= 1) {
        s  += __shfl_down_sync(0xffffffffu, s,  o);
        ss += __shfl_down_sync(0xffffffffu, ss, o);
    }

    __shared__ float red_s[6], red_ss[6], stat[2];
    const int warp = tid >> 5, lane = tid & 31;
    if (lane == 0) { red_s[warp] = s; red_ss[warp] = ss; }
    __syncthreads();
    if (tid == 0) {
        float S = 0.f, SS = 0.f;
        #pragma unroll
        for (int i = 0; i < 6; i++) { S += red_s[i]; SS += red_ss[i]; }
        const float mean = S * (1.0f / DDIM);
        const float var  = SS * (1.0f / DDIM) - mean * mean;
        stat[0] = mean;
        stat[1] = rsqrtf(var + LN_EPS);
    }
    __syncthreads();
    const float mean = stat[0], rstd = stat[1];

    const float4 g = __ldg((const float4*)ln_gamma + tid);
    const float4 b = __ldg((const float4*)ln_beta  + tid);
    float ox = (ax - mean) * rstd * g.x + b.x;
    float oy = (ay - mean) * rstd * g.y + b.y;
    float oz = (az - mean) * rstd * g.z + b.z;
    float ow = (aw - mean) * rstd * g.w + b.w;

    __nv_bfloat16 hx = __float2bfloat16_rn(ox), hy = __float2bfloat16_rn(oy);
    __nv_bfloat16 hz = __float2bfloat16_rn(oz), hw = __float2bfloat16_rn(ow);
    __nv_bfloat16 lx = __float2bfloat16_rn(ox - __bfloat162float(hx));
    __nv_bfloat16 ly = __float2bfloat16_rn(oy - __bfloat162float(hy));
    __nv_bfloat16 lz = __float2bfloat16_rn(oz - __bfloat162float(hz));
    __nv_bfloat16 lw = __float2bfloat16_rn(ow - __bfloat162float(hw));

    // SW128 tile, hi/lo K-interleaved: row = 128 B; hi at bytes [0,64), lo [64,128).
    const int tile  = slot >> 7;                // 128-row A tile
    const int row   = slot & 127;
    const int chunk = tid >> 3;                 // k-chunk (32 k per chunk)
    const int kc8   = (tid & 7) * 8;            // byte offset within 64B half-row
    const uint32_t off_h = (uint32_t)(row * 128 + kc8);
    const uint32_t off_l = off_h + 64;
    const size_t tbase = (size_t)(tile * NCHUNK + chunk) * SZ_TA;

    uint2 hv, lv;
    ((__nv_bfloat162*)&hv)[0] = __halves2bfloat162(hx, hy);
    ((__nv_bfloat162*)&hv)[1] = __halves2bfloat162(hz, hw);
    ((__nv_bfloat162*)&lv)[0] = __halves2bfloat162(lx, ly);
    ((__nv_bfloat162*)&lv)[1] = __halves2bfloat162(lz, lw);
    *(uint2*)((char*)g_a + tbase + sw128(off_h)) = hv;
    *(uint2*)((char*)g_a + tbase + sw128(off_l)) = lv;
}

// ======================= kernel 2: split proj_w (SW128 interleaved tiles) =====
__global__ void __launch_bounds__(256) wsplit_kernel(const float* __restrict__ W) {
    const int i = blockIdx.x * blockDim.x + threadIdx.x;   // float4 index
    const float4 v = __ldg((const float4*)W + i);
    __nv_bfloat16 hx = __float2bfloat16_rn(v.x), hy = __float2bfloat16_rn(v.y);
    __nv_bfloat16 hz = __float2bfloat16_rn(v.z), hw = __float2bfloat16_rn(v.w);
    __nv_bfloat16 lx = __float2bfloat16_rn(v.x - __bfloat162float(hx));
    __nv_bfloat16 ly = __float2bfloat16_rn(v.y - __bfloat162float(hy));
    __nv_bfloat16 lz = __float2bfloat16_rn(v.z - __bfloat162float(hz));
    __nv_bfloat16 lw = __float2bfloat16_rn(v.w - __bfloat162float(hw));

    const int row   = i / (DDIM / 4);           // output feature 0..767
    const int col4  = i % (DDIM / 4);
    const int chunk = col4 >> 3;
    const int kc8   = (col4 & 7) * 8;
    const int tile  = row >> 8;                 // 256-row W tile, 0..2
    const int lrow  = row & 255;
    const uint32_t off_h = (uint32_t)(lrow * 128 + kc8);
    const uint32_t off_l = off_h + 64;
    const size_t tbase = (size_t)(tile * NCHUNK + chunk) * SZ_TB;

    uint2 hv, lv;
    ((__nv_bfloat162*)&hv)[0] = __halves2bfloat162(hx, hy);
    ((__nv_bfloat162*)&hv)[1] = __halves2bfloat162(hz, hw);
    ((__nv_bfloat162*)&lv)[0] = __halves2bfloat162(lx, ly);
    ((__nv_bfloat162*)&lv)[1] = __halves2bfloat162(lz, lw);
    *(uint2*)((char*)g_w + tbase + sw128(off_h)) = hv;
    *(uint2*)((char*)g_w + tbase + sw128(off_l)) = lv;
}

// ======================= kernel 3: tcgen05 GEMM (single-thread control) =======
#define OFF_TM   0
#define OFF_FULL 16                    // 4 full barriers
#define OFF_MMA  48                    // 4 mma barriers
#define OFF_DATA 1024
#define GEMM_SMEM (OFF_DATA + NBUF*SZ_BUF)   // 197632

__global__ void __launch_bounds__(256, 1) gemm_tc_kernel(
    const float* __restrict__ bias, float* __restrict__ C,
    int tail_start, int total_out)
{
#if HAS_TCGEN05
    extern __shared__ char smem[];
    const uint32_t sb  = smem_u32(smem);
    const int tid = threadIdx.x;
    const int bn  = blockIdx.x;   // 0..2
    const int bm  = blockIdx.y;   // 0..31

    if (bn == 0 && bm == 0) {
        for (int i = tail_start + tid; i < total_out; i += 256) C[i] = 0.0f;
    }

    if (tid < 32) {
        TCGEN05_ALLOC(sb + OFF_TM, 256);
        TCGEN05_RELINQ();
    }
    __syncthreads();
    uint32_t tmem;
    asm volatile("ld.shared.b32 %0, [%1];" : "=r"(tmem) : "r"(sb + OFF_TM));

    if (tid == 0) {
        #pragma unroll
        for (int i = 0; i < NBUF; i++) {
            MBARRIER_INIT(sb + OFF_FULL + i * 8, 1);
            MBARRIER_INIT(sb + OFF_MMA  + i * 8, 1);
        }
        FENCE_PROXY_ASYNC();

        const char* aT = (const char*)g_a + (size_t)bm * NCHUNK * SZ_TA;
        const char* bT = (const char*)g_w + (size_t)bn * NCHUNK * SZ_TB;

        auto load_chunk = [&](int c) {
            const int buf = c & (NBUF - 1);
            const uint32_t base = sb + OFF_DATA + buf * SZ_BUF;
            const uint32_t fm   = sb + OFF_FULL + buf * 8;
            MBARRIER_EXPECT_TX(fm, SZ_BUF);
            CP_BULK_G2S(base,         aT + (size_t)c * SZ_TA, SZ_TA, fm);
            CP_BULK_G2S(base + SZ_TA, bT + (size_t)c * SZ_TB, SZ_TB, fm);
        };

        load_chunk(0);
        load_chunk(1);
        load_chunk(2);

        // idesc: F32 accum, BF16xBF16, N=256, M=128 (cg1)
        const uint32_t idesc = (1u << 4) | (1u << 7) | (1u << 10) |
                               ((256 / 8) << 17) | ((128 / 16) << 24);

        for (int c = 0; c < NCHUNK; c++) {
            const int buf = c & (NBUF - 1);
            MBARRIER_WAIT_PARITY(sb + OFF_FULL + buf * 8, (uint32_t)((c >> 2) & 1));

            const uint32_t base = sb + OFF_DATA + buf * SZ_BUF;
            const uint64_t dA = make_desc_sw128(base);
            const uint64_t dB = make_desc_sw128(base + SZ_TA);
            #pragma unroll
            for (int ks = 0; ks < 2; ks++) {
                const uint64_t oh = ks * 2;       // hi K=16 slice
                const uint64_t ol = 4 + ks * 2;   // lo K=16 slice
                mma_bf16_ss(tmem, dA + oh, dB + oh, idesc, (c | ks) != 0);
                mma_bf16_ss(tmem, dA + oh, dB + ol, idesc, 1u);
                mma_bf16_ss(tmem, dA + ol, dB + oh, idesc, 1u);
            }
            TCGEN05_COMMIT(sb + OFF_MMA + buf * 8);

            if (c + LEAD < NCHUNK) {
                const int cc = c + LEAD - NBUF;   // previous occupant of target buf
                if (cc >= 0) {
                    MBARRIER_WAIT_PARITY(sb + OFF_MMA + (cc & (NBUF - 1)) * 8,
                                         (uint32_t)((cc >> 2) & 1));
                }
                load_chunk(c + LEAD);
            }
        }
        const int cl = NCHUNK - 1;
        MBARRIER_WAIT_PARITY(sb + OFF_MMA + (cl & (NBUF - 1)) * 8,
                             (uint32_t)((cl >> 2) & 1));
    }

    __syncthreads();
    TCGEN05_FENCE_AFTER();

    // -------- epilogue: 2 LDTM x32 in flight per wait --------
    const int w    = tid >> 5, lane = tid & 31;
    const int part = w & 3,    half = w >> 2;
    const int row  = bm * 128 + part * 32 + lane;
    float* crow = C + (size_t)row * DDIM;

    #pragma unroll
    for (int pair = 0; pair < 2; pair++) {
        const int colbase = half * 128 + pair * 64;
        uint32_t r0[32], r1[32];
        TCGEN05_LD_X32(r0, tmem + colbase);
        TCGEN05_LD_X32(r1, tmem + colbase + 32);
        TCGEN05_WAIT_LD();
        const int gcol0 = bn * 256 + colbase;
        #pragma unroll
        for (int i = 0; i < 32; i += 4) {
            const float4 bv = __ldg((const float4*)(bias + gcol0 + i));
            float4 o;
            o.x = __uint_as_float(r0[i + 0]) + bv.x;
            o.y = __uint_as_float(r0[i + 1]) + bv.y;
            o.z = __uint_as_float(r0[i + 2]) + bv.z;
            o.w = __uint_as_float(r0[i + 3]) + bv.w;
            *(float4*)(crow + gcol0 + i) = o;
        }
        #pragma unroll
        for (int i = 0; i < 32; i += 4) {
            const float4 bv = __ldg((const float4*)(bias + gcol0 + 32 + i));
            float4 o;
            o.x = __uint_as_float(r1[i + 0]) + bv.x;
            o.y = __uint_as_float(r1[i + 1]) + bv.y;
            o.z = __uint_as_float(r1[i + 2]) + bv.z;
            o.w = __uint_as_float(r1[i + 3]) + bv.w;
            *(float4*)(crow + gcol0 + 32 + i) = o;
        }
    }

    __syncthreads();
    if (tid < 32) TCGEN05_DEALLOC(tmem, 256);
#endif // HAS_TCGEN05
}

// ======================= launch =======================
extern "C" void kernel_launch(void* const* d_in, const int* in_sizes, int n_in,
                              void* d_out, int out_size) {
    const int*   token_ids         = (const int*)  d_in[0];
    const int*   segment_ids       = (const int*)  d_in[1];
    const int*   section_ids       = (const int*)  d_in[2];
    const int*   temporality_ids   = (const int*)  d_in[3];
    const int*   negation_ids      = (const int*)  d_in[4];
    const int*   position_ids      = (const int*)  d_in[5];
    const int*   timestamp_ids     = (const int*)  d_in[6];
    const float* token_table       = (const float*)d_in[7];
    const float* section_table     = (const float*)d_in[8];
    const float* temporality_table = (const float*)d_in[9];
    const float* negation_table    = (const float*)d_in[10];
    const float* position_table    = (const float*)d_in[11];
    const float* timestamp_table   = (const float*)d_in[12];
    const float* ln_gamma          = (const float*)d_in[13];
    const float* ln_beta           = (const float*)d_in[14];
    const float* proj_w            = (const float*)d_in[15];
    const float* proj_b            = (const float*)d_in[16];

    float* out = (float*)d_out;

    cudaFuncSetAttribute(gemm_tc_kernel,
                         cudaFuncAttributeMaxDynamicSharedMemorySize, GEMM_SMEM);

    segstart_kernel<<<NTOK / 256, 256>>>(segment_ids);

    wsplit_kernel<<<(DDIM * DDIM / 4) / 256, 256>>>(proj_w);

    embed_ln_kernel<<<NSLOT, 192>>>(
        token_ids, section_ids, temporality_ids, negation_ids,
        position_ids, timestamp_ids, token_table, section_table,
        temporality_table, negation_table, position_table, timestamp_table,
        ln_gamma, ln_beta);

    dim3 grid_tc(DDIM / 256, NSLOT / 128);   // (3, 32)
    gemm_tc_kernel<<<grid_tc, 256, GEMM_SMEM>>>(proj_b, out,
                                                NSLOT * DDIM, out_size);
}